// round 4
// baseline (speedup 1.0000x reference)
#include <cuda_runtime.h>
#include <math.h>

#define Nn 50000
#define Ee 600000
#define Dd 128

typedef unsigned long long ull;

// Scratch (allocation-free rule: __device__ globals)
__device__ float g_m[Nn * Dd];     // per-node messages
__device__ float g_sum[Nn * Dd];   // scatter accumulation
__device__ float g_cnt[Nn];        // in-degree

// Packed fp32x2 FMA (Blackwell; ptxas never auto-fuses this)
#define FMA2(d, a, b) \
    asm("fma.rn.f32x2 %0, %1, %2, %3;" : "=l"(d) : "l"(a), "l"(b), "l"(d))

__device__ __forceinline__ ull splat2(float x) {
    ull d;
    asm("mov.b64 %0, {%1, %1};" : "=l"(d) : "f"(x));
    return d;
}
__device__ __forceinline__ void unpack2(ull v, float& lo, float& hi) {
    asm("mov.b64 {%0, %1}, %2;" : "=f"(lo), "=f"(hi) : "l"(v));
}

// ---------------------------------------------------------------------------
// GEMM core: 128 rows x 128 cols, A pre-splatted {v,v} in smem (row-major,
// [r][k] as u64), W [k][c] fp32. 512 threads: tx=tid&15 (8 cols), ty=tid>>4
// (4 rows). Accumulator: 4 rows x 4 col-pairs of f32x2.
// ---------------------------------------------------------------------------
__device__ __forceinline__ void gemm_f32x2(const ull* __restrict__ sA2,
                                           const float* __restrict__ sW,
                                           int tx, int ty, ull acc[4][4]) {
    const ull* a_base = sA2 + (ty << 2) * 128;
    const float* w_base = sW + (tx << 3);
#pragma unroll 4
    for (int k = 0; k < 128; k++) {
        ull a0 = a_base[k];
        ull a1 = a_base[128 + k];
        ull a2 = a_base[256 + k];
        ull a3 = a_base[384 + k];
        ulonglong2 w01 = *reinterpret_cast<const ulonglong2*>(w_base + k * 128);
        ulonglong2 w23 = *reinterpret_cast<const ulonglong2*>(w_base + k * 128 + 4);
        FMA2(acc[0][0], a0, w01.x); FMA2(acc[0][1], a0, w01.y);
        FMA2(acc[0][2], a0, w23.x); FMA2(acc[0][3], a0, w23.y);
        FMA2(acc[1][0], a1, w01.x); FMA2(acc[1][1], a1, w01.y);
        FMA2(acc[1][2], a1, w23.x); FMA2(acc[1][3], a1, w23.y);
        FMA2(acc[2][0], a2, w01.x); FMA2(acc[2][1], a2, w01.y);
        FMA2(acc[2][2], a2, w23.x); FMA2(acc[2][3], a2, w23.y);
        FMA2(acc[3][0], a3, w01.x); FMA2(acc[3][1], a3, w01.y);
        FMA2(acc[3][2], a3, w23.x); FMA2(acc[3][3], a3, w23.y);
    }
}

// ---------------------------------------------------------------------------
// Fused 2-layer MLP over [128,128] row blocks.
// MODE 0: in = logmap0(x), out = g_m ; also zeroes g_sum/g_cnt for its rows.
// MODE 1: in = g_sum/(g_cnt+eps), out = expmap0(mlp(...)) -> Out
// Dynamic smem: sW (64 KB fp32) + sA2 (128 KB u64 splatted) = 192 KB.
// ---------------------------------------------------------------------------
template <int MODE>
__global__ __launch_bounds__(512, 1) void mlp_kernel(
    const float* __restrict__ X,
    const float* __restrict__ W1, const float* __restrict__ B1,
    const float* __restrict__ W2, const float* __restrict__ B2,
    float* __restrict__ Out) {
    extern __shared__ unsigned char smem_raw[];
    float* sW = reinterpret_cast<float*>(smem_raw);             // 128*128 f32
    ull* sA2 = reinterpret_cast<ull*>(smem_raw + 65536);        // 128*128 u64
    __shared__ float sB1[128], sB2[128];

    const int tid = threadIdx.x;
    const int warp = tid >> 5, lane = tid & 31;
    const int tx = tid & 15, ty = tid >> 4;
    const int row0 = blockIdx.x * 128;

    const float* Xin = (MODE == 0) ? X : (const float*)g_sum;
    float* Op = (MODE == 0) ? (float*)g_m : Out;

    // MODE 0: zero this block's slice of the accumulators (overlaps staging)
    if (MODE == 0) {
        float4 z = make_float4(0.f, 0.f, 0.f, 0.f);
#pragma unroll
        for (int i = 0; i < 8; i++) {
            int e = row0 * 128 + (tid + i * 512) * 4;
            if (e < Nn * Dd) *reinterpret_cast<float4*>(g_sum + e) = z;
        }
        if (tid < 128 && row0 + tid < Nn) g_cnt[row0 + tid] = 0.f;
    }

    // ---- stage W1 + biases ----
    {
        const float4* src = reinterpret_cast<const float4*>(W1);
        float4* dst = reinterpret_cast<float4*>(sW);
        for (int i = tid; i < 128 * 32; i += 512) dst[i] = src[i];
    }
    if (tid < 128) sB1[tid] = B1[tid];
    else if (tid < 256) sB2[tid - 128] = B2[tid - 128];

    // ---- stage input block (splatted, row-major) with input transform ----
    for (int rr = warp; rr < 128; rr += 16) {
        const int r = row0 + rr;
        float4 v = make_float4(0.f, 0.f, 0.f, 0.f);
        if (r < Nn) {
            v = reinterpret_cast<const float4*>(Xin + (size_t)r * 128)[lane];
            if (MODE == 1) {
                float inv = 1.f / (g_cnt[r] + 1e-8f);
                v.x *= inv; v.y *= inv; v.z *= inv; v.w *= inv;
            }
        }
        if (MODE == 0) {
            float ss = v.x * v.x + v.y * v.y + v.z * v.z + v.w * v.w;
#pragma unroll
            for (int o = 16; o > 0; o >>= 1)
                ss += __shfl_xor_sync(0xffffffffu, ss, o);
            float nrm = sqrtf(ss);
            float nc = fminf(fmaxf(nrm, 1e-8f), 1.f - 1e-5f);
            float f = atanhf(nc) / nc;
            v.x *= f; v.y *= f; v.z *= f; v.w *= f;
        }
        ull* dst = sA2 + rr * 128 + lane * 4;
        ulonglong2 p01; p01.x = splat2(v.x); p01.y = splat2(v.y);
        ulonglong2 p23; p23.x = splat2(v.z); p23.y = splat2(v.w);
        reinterpret_cast<ulonglong2*>(dst)[0] = p01;
        reinterpret_cast<ulonglong2*>(dst)[1] = p23;
    }
    __syncthreads();

    // ---- phase 1: hidden = relu(A @ W1 + b1) ----
    ull acc[4][4];
#pragma unroll
    for (int i = 0; i < 4; i++)
#pragma unroll
        for (int p = 0; p < 4; p++) acc[i][p] = splat2(0.f);

    gemm_f32x2(sA2, sW, tx, ty, acc);
    __syncthreads();   // all reads of sA2/sW complete

    // stage W2
    {
        const float4* src = reinterpret_cast<const float4*>(W2);
        float4* dst = reinterpret_cast<float4*>(sW);
        for (int i = tid; i < 128 * 32; i += 512) dst[i] = src[i];
    }
    // write H (splatted) back into sA2
#pragma unroll
    for (int i = 0; i < 4; i++) {
        ull* dst = sA2 + (ty * 4 + i) * 128 + tx * 8;
        ulonglong2 q01, q23;
        float lo, hi;
        unpack2(acc[i][0], lo, hi);
        q01.x = splat2(fmaxf(lo + sB1[tx * 8 + 0], 0.f));
        q01.y = splat2(fmaxf(hi + sB1[tx * 8 + 1], 0.f));
        unpack2(acc[i][1], lo, hi);
        q23.x = splat2(fmaxf(lo + sB1[tx * 8 + 2], 0.f));
        q23.y = splat2(fmaxf(hi + sB1[tx * 8 + 3], 0.f));
        reinterpret_cast<ulonglong2*>(dst)[0] = q01;
        reinterpret_cast<ulonglong2*>(dst)[1] = q23;
        unpack2(acc[i][2], lo, hi);
        q01.x = splat2(fmaxf(lo + sB1[tx * 8 + 4], 0.f));
        q01.y = splat2(fmaxf(hi + sB1[tx * 8 + 5], 0.f));
        unpack2(acc[i][3], lo, hi);
        q23.x = splat2(fmaxf(lo + sB1[tx * 8 + 6], 0.f));
        q23.y = splat2(fmaxf(hi + sB1[tx * 8 + 7], 0.f));
        reinterpret_cast<ulonglong2*>(dst)[2] = q01;
        reinterpret_cast<ulonglong2*>(dst)[3] = q23;
    }
    __syncthreads();

    // ---- phase 2: out = H @ W2 + b2 ----
#pragma unroll
    for (int i = 0; i < 4; i++)
#pragma unroll
        for (int p = 0; p < 4; p++) acc[i][p] = splat2(0.f);

    gemm_f32x2(sA2, sW, tx, ty, acc);

    // ---- epilogue: bias (+ expmap0 for MODE 1) + store ----
#pragma unroll
    for (int i = 0; i < 4; i++) {
        float o[8];
#pragma unroll
        for (int p = 0; p < 4; p++) {
            float lo, hi;
            unpack2(acc[i][p], lo, hi);
            o[2 * p]     = lo + sB2[tx * 8 + 2 * p];
            o[2 * p + 1] = hi + sB2[tx * 8 + 2 * p + 1];
        }
        if (MODE == 1) {
            float ss = 0.f;
#pragma unroll
            for (int j = 0; j < 8; j++) ss += o[j] * o[j];
            ss += __shfl_xor_sync(0xffffffffu, ss, 1);
            ss += __shfl_xor_sync(0xffffffffu, ss, 2);
            ss += __shfl_xor_sync(0xffffffffu, ss, 4);
            ss += __shfl_xor_sync(0xffffffffu, ss, 8);
            float nrm = sqrtf(ss);
            float nc = fmaxf(nrm, 1e-8f);
            float f = tanhf(nc) / nc;
#pragma unroll
            for (int j = 0; j < 8; j++) o[j] *= f;
        }
        const int r = row0 + ty * 4 + i;
        if (r < Nn) {
            float* p = Op + (size_t)r * 128 + tx * 8;
            *reinterpret_cast<float4*>(p)     = make_float4(o[0], o[1], o[2], o[3]);
            *reinterpret_cast<float4*>(p + 4) = make_float4(o[4], o[5], o[6], o[7]);
        }
    }
}

// ---------------------------------------------------------------------------
// Scatter: one warp per edge. g_sum[dst] += g_m[src]; g_cnt[dst] += 1.
// ---------------------------------------------------------------------------
__global__ __launch_bounds__(256) void scatter_kernel(const int* __restrict__ ei) {
    const int gw = (blockIdx.x * blockDim.x + threadIdx.x) >> 5;
    const int lane = threadIdx.x & 31;
    if (gw >= Ee) return;
    const int dst = ei[gw];         // edge_index[0] = row
    const int src = ei[Ee + gw];    // edge_index[1] = col
    float4 v = reinterpret_cast<const float4*>(g_m + (size_t)src * 128)[lane];
    float* p = g_sum + (size_t)dst * 128 + lane * 4;
    asm volatile("red.global.add.v4.f32 [%0], {%1,%2,%3,%4};"
                 :: "l"(p), "f"(v.x), "f"(v.y), "f"(v.z), "f"(v.w)
                 : "memory");
    if (lane == 0) atomicAdd(&g_cnt[dst], 1.0f);
}

// ---------------------------------------------------------------------------
extern "C" void kernel_launch(void* const* d_in, const int* in_sizes, int n_in,
                              void* d_out, int out_size) {
    const float* x  = (const float*)d_in[0];
    const int*   ei = (const int*)d_in[1];
    const float* w1 = (const float*)d_in[2];
    const float* b1 = (const float*)d_in[3];
    const float* w2 = (const float*)d_in[4];
    const float* b2 = (const float*)d_in[5];
    const float* w3 = (const float*)d_in[6];
    const float* b3 = (const float*)d_in[7];
    const float* w4 = (const float*)d_in[8];
    const float* b4 = (const float*)d_in[9];
    float* out = (float*)d_out;

    const size_t shmem = 65536 + (size_t)128 * 128 * 8;   // 192 KB
    static bool configured = false;
    if (!configured) {
        cudaFuncSetAttribute(mlp_kernel<0>, cudaFuncAttributeMaxDynamicSharedMemorySize, (int)shmem);
        cudaFuncSetAttribute(mlp_kernel<1>, cudaFuncAttributeMaxDynamicSharedMemorySize, (int)shmem);
        configured = true;
    }

    const int mlp_blocks = (Nn + 127) / 128;  // 391

    mlp_kernel<0><<<mlp_blocks, 512, shmem>>>(x, w1, b1, w2, b2, nullptr);
    scatter_kernel<<<Ee / 8, 256>>>(ei);
    mlp_kernel<1><<<mlp_blocks, 512, shmem>>>(nullptr, w3, b3, w4, b4, out);
}

// round 5
// speedup vs baseline: 1.2786x; 1.2786x over previous
#include <cuda_runtime.h>
#include <math.h>

#define Nn 50000
#define Ee 600000
#define Dd 128
#define ROWS 256          // rows per CTA
#define SAS 258           // sA stride in floats (1032 B: 8B-aligned, odd bank group)

typedef unsigned long long ull;

// Scratch (allocation-free rule: __device__ globals)
__device__ float g_m[Nn * Dd];     // per-node messages
__device__ float g_sum[Nn * Dd];   // scatter accumulation
__device__ float g_cnt[Nn];        // in-degree

// Packed fp32x2 FMA (Blackwell; ptxas never auto-fuses this)
#define FMA2(d, a, b) \
    asm("fma.rn.f32x2 %0, %1, %2, %3;" : "=l"(d) : "l"(a), "l"(b), "l"(d))

__device__ __forceinline__ ull splat2(float x) {
    ull d;
    asm("mov.b64 %0, {%1, %1};" : "=l"(d) : "f"(x));
    return d;
}
__device__ __forceinline__ ull pack2(float lo, float hi) {
    ull d;
    asm("mov.b64 %0, {%1, %2};" : "=l"(d) : "f"(lo), "f"(hi));
    return d;
}
__device__ __forceinline__ void unpack2(ull v, float& lo, float& hi) {
    asm("mov.b64 {%0, %1}, %2;" : "=f"(lo), "=f"(hi) : "l"(v));
}

// ---------------------------------------------------------------------------
// GEMM core: 256 rows x 128 cols. A fp32 k-major [k][SAS] — row-PAIRS are
// loaded directly as u64 FFMA2 operands (no splat traffic). W fp32 [k][128],
// splatted per-column into registers. 512 threads: tx=tid&15 (8 cols each),
// ty=tid>>4 (8 rows each). acc[rp][c] = f32x2 over rows (2rp, 2rp+1).
// ---------------------------------------------------------------------------
__device__ __forceinline__ void gemm_rp(const float* __restrict__ sA,
                                        const float* __restrict__ sW,
                                        int tx, int ty, ull acc[4][8]) {
    const float* a_base = sA + (ty << 3);
    const float* w_base = sW + (tx << 3);
#pragma unroll 2
    for (int k = 0; k < 128; k++) {
        const float* ap = a_base + k * SAS;
        ull a0 = *reinterpret_cast<const ull*>(ap);
        ull a1 = *reinterpret_cast<const ull*>(ap + 2);
        ull a2 = *reinterpret_cast<const ull*>(ap + 4);
        ull a3 = *reinterpret_cast<const ull*>(ap + 6);
        float4 w0 = *reinterpret_cast<const float4*>(w_base + k * 128);
        float4 w1 = *reinterpret_cast<const float4*>(w_base + k * 128 + 4);
        ull ws[8];
        ws[0] = splat2(w0.x); ws[1] = splat2(w0.y);
        ws[2] = splat2(w0.z); ws[3] = splat2(w0.w);
        ws[4] = splat2(w1.x); ws[5] = splat2(w1.y);
        ws[6] = splat2(w1.z); ws[7] = splat2(w1.w);
#pragma unroll
        for (int c = 0; c < 8; c++) {
            FMA2(acc[0][c], a0, ws[c]);
            FMA2(acc[1][c], a1, ws[c]);
            FMA2(acc[2][c], a2, ws[c]);
            FMA2(acc[3][c], a3, ws[c]);
        }
    }
}

// ---------------------------------------------------------------------------
// Fused 2-layer MLP over [256,128] row blocks.
// MODE 0: in = logmap0(x), out = g_m ; also zeroes g_sum/g_cnt for its rows.
// MODE 1: in = g_sum/(g_cnt+eps), out = expmap0(mlp(...)) -> Out
// Dynamic smem: sW 64 KB + sA 128*SAS*4 = 132 KB  -> 197.6 KB, 1 CTA/SM.
// ---------------------------------------------------------------------------
template <int MODE>
__global__ __launch_bounds__(512, 1) void mlp_kernel(
    const float* __restrict__ X,
    const float* __restrict__ W1, const float* __restrict__ B1,
    const float* __restrict__ W2, const float* __restrict__ B2,
    float* __restrict__ Out) {
    extern __shared__ float smem[];
    float* sW = smem;                 // [k*128 + c]
    float* sA = smem + 128 * 128;     // [k*SAS + r], r in [0,256)
    __shared__ float sB1[128], sB2[128];

    const int tid = threadIdx.x;
    const int warp = tid >> 5, lane = tid & 31;
    const int tx = tid & 15, ty = tid >> 4;   // ty in [0,32)
    const int row0 = blockIdx.x * ROWS;

    const float* Xin = (MODE == 0) ? X : (const float*)g_sum;
    float* Op = (MODE == 0) ? (float*)g_m : Out;

    // MODE 0: zero this block's slice of the accumulators
    if (MODE == 0) {
        float4 z = make_float4(0.f, 0.f, 0.f, 0.f);
#pragma unroll
        for (int i = 0; i < 16; i++) {
            int e = row0 * 128 + (tid + i * 512) * 4;
            if (e < Nn * Dd) *reinterpret_cast<float4*>(g_sum + e) = z;
        }
        if (tid < ROWS && row0 + tid < Nn) g_cnt[row0 + tid] = 0.f;
    }

    // ---- stage W1 + biases ----
    {
        const float4* src = reinterpret_cast<const float4*>(W1);
        float4* dst = reinterpret_cast<float4*>(sW);
#pragma unroll
        for (int i = 0; i < 8; i++) dst[tid + i * 512] = src[tid + i * 512];
    }
    if (tid < 128) sB1[tid] = B1[tid];
    else if (tid < 256) sB2[tid - 128] = B2[tid - 128];

    // ---- stage input block (fp32, k-major) with input transform ----
    for (int rr = warp; rr < ROWS; rr += 16) {
        const int r = row0 + rr;
        float4 v = make_float4(0.f, 0.f, 0.f, 0.f);
        if (r < Nn) {
            v = reinterpret_cast<const float4*>(Xin + (size_t)r * 128)[lane];
            if (MODE == 1) {
                float inv = 1.f / (g_cnt[r] + 1e-8f);
                v.x *= inv; v.y *= inv; v.z *= inv; v.w *= inv;
            }
        }
        if (MODE == 0) {
            float ss = v.x * v.x + v.y * v.y + v.z * v.z + v.w * v.w;
#pragma unroll
            for (int o = 16; o > 0; o >>= 1)
                ss += __shfl_xor_sync(0xffffffffu, ss, o);
            float nrm = sqrtf(ss);
            float nc = fminf(fmaxf(nrm, 1e-8f), 1.f - 1e-5f);
            float f = atanhf(nc) / nc;
            v.x *= f; v.y *= f; v.z *= f; v.w *= f;
        }
        const int k0 = lane * 4;
        sA[(k0 + 0) * SAS + rr] = v.x;
        sA[(k0 + 1) * SAS + rr] = v.y;
        sA[(k0 + 2) * SAS + rr] = v.z;
        sA[(k0 + 3) * SAS + rr] = v.w;
    }
    __syncthreads();

    // ---- phase 1: hidden = relu(A @ W1 + b1) ----
    ull acc[4][8];
#pragma unroll
    for (int rp = 0; rp < 4; rp++)
#pragma unroll
        for (int c = 0; c < 8; c++) acc[rp][c] = 0ull;

    gemm_rp(sA, sW, tx, ty, acc);
    __syncthreads();   // all reads of sA/sW complete

    // stage W2 + write H (k-major, row-pair u64 stores) back into sA
    {
        const float4* src = reinterpret_cast<const float4*>(W2);
        float4* dst = reinterpret_cast<float4*>(sW);
#pragma unroll
        for (int i = 0; i < 8; i++) dst[tid + i * 512] = src[tid + i * 512];
    }
#pragma unroll
    for (int c = 0; c < 8; c++) {
        const int hc = tx * 8 + c;
        const float b = sB1[hc];
#pragma unroll
        for (int rp = 0; rp < 4; rp++) {
            float lo, hi;
            unpack2(acc[rp][c], lo, hi);
            lo = fmaxf(lo + b, 0.f);
            hi = fmaxf(hi + b, 0.f);
            *reinterpret_cast<ull*>(sA + hc * SAS + ty * 8 + rp * 2) = pack2(lo, hi);
        }
    }
    __syncthreads();

    // ---- phase 2: out = H @ W2 + b2 ----
#pragma unroll
    for (int rp = 0; rp < 4; rp++)
#pragma unroll
        for (int c = 0; c < 8; c++) acc[rp][c] = 0ull;

    gemm_rp(sA, sW, tx, ty, acc);

    // ---- epilogue: bias (+ expmap0 for MODE 1) + store ----
#pragma unroll
    for (int rp = 0; rp < 4; rp++) {
        float olo[8], ohi[8];
#pragma unroll
        for (int c = 0; c < 8; c++) {
            float lo, hi;
            unpack2(acc[rp][c], lo, hi);
            olo[c] = lo + sB2[tx * 8 + c];
            ohi[c] = hi + sB2[tx * 8 + c];
        }
        if (MODE == 1) {
            float sl = 0.f, sh = 0.f;
#pragma unroll
            for (int c = 0; c < 8; c++) { sl += olo[c] * olo[c]; sh += ohi[c] * ohi[c]; }
            // reduce across the 16 tx threads sharing these rows (half-warp)
#pragma unroll
            for (int o = 1; o < 16; o <<= 1) {
                sl += __shfl_xor_sync(0xffffffffu, sl, o);
                sh += __shfl_xor_sync(0xffffffffu, sh, o);
            }
            float ncl = fmaxf(sqrtf(sl), 1e-8f);
            float nch = fmaxf(sqrtf(sh), 1e-8f);
            float fl = tanhf(ncl) / ncl;
            float fh = tanhf(nch) / nch;
#pragma unroll
            for (int c = 0; c < 8; c++) { olo[c] *= fl; ohi[c] *= fh; }
        }
        const int r = row0 + ty * 8 + rp * 2;
        if (r < Nn) {
            float* p = Op + (size_t)r * 128 + tx * 8;
            *reinterpret_cast<float4*>(p)     = make_float4(olo[0], olo[1], olo[2], olo[3]);
            *reinterpret_cast<float4*>(p + 4) = make_float4(olo[4], olo[5], olo[6], olo[7]);
        }
        if (r + 1 < Nn) {
            float* p = Op + (size_t)(r + 1) * 128 + tx * 8;
            *reinterpret_cast<float4*>(p)     = make_float4(ohi[0], ohi[1], ohi[2], ohi[3]);
            *reinterpret_cast<float4*>(p + 4) = make_float4(ohi[4], ohi[5], ohi[6], ohi[7]);
        }
    }
}

// ---------------------------------------------------------------------------
// Scatter: one warp per edge. g_sum[dst] += g_m[src]; g_cnt[dst] += 1.
// ---------------------------------------------------------------------------
__global__ __launch_bounds__(256) void scatter_kernel(const int* __restrict__ ei) {
    const int gw = (blockIdx.x * blockDim.x + threadIdx.x) >> 5;
    const int lane = threadIdx.x & 31;
    if (gw >= Ee) return;
    const int dst = ei[gw];         // edge_index[0] = row
    const int src = ei[Ee + gw];    // edge_index[1] = col
    float4 v = reinterpret_cast<const float4*>(g_m + (size_t)src * 128)[lane];
    float* p = g_sum + (size_t)dst * 128 + lane * 4;
    asm volatile("red.global.add.v4.f32 [%0], {%1,%2,%3,%4};"
                 :: "l"(p), "f"(v.x), "f"(v.y), "f"(v.z), "f"(v.w)
                 : "memory");
    if (lane == 0) atomicAdd(&g_cnt[dst], 1.0f);
}

// ---------------------------------------------------------------------------
extern "C" void kernel_launch(void* const* d_in, const int* in_sizes, int n_in,
                              void* d_out, int out_size) {
    const float* x  = (const float*)d_in[0];
    const int*   ei = (const int*)d_in[1];
    const float* w1 = (const float*)d_in[2];
    const float* b1 = (const float*)d_in[3];
    const float* w2 = (const float*)d_in[4];
    const float* b2 = (const float*)d_in[5];
    const float* w3 = (const float*)d_in[6];
    const float* b3 = (const float*)d_in[7];
    const float* w4 = (const float*)d_in[8];
    const float* b4 = (const float*)d_in[9];
    float* out = (float*)d_out;

    const size_t shmem = (size_t)(128 * 128 + 128 * SAS) * sizeof(float);  // 197632 B
    static bool configured = false;
    if (!configured) {
        cudaFuncSetAttribute(mlp_kernel<0>, cudaFuncAttributeMaxDynamicSharedMemorySize, (int)shmem);
        cudaFuncSetAttribute(mlp_kernel<1>, cudaFuncAttributeMaxDynamicSharedMemorySize, (int)shmem);
        configured = true;
    }

    const int mlp_blocks = (Nn + ROWS - 1) / ROWS;  // 196

    mlp_kernel<0><<<mlp_blocks, 512, shmem>>>(x, w1, b1, w2, b2, nullptr);
    scatter_kernel<<<Ee / 8, 256>>>(ei);
    mlp_kernel<1><<<mlp_blocks, 512, shmem>>>(nullptr, w3, b3, w4, b4, out);
}